// round 4
// baseline (speedup 1.0000x reference)
#include <cuda_runtime.h>
#include <math.h>

// Problem constants
#define BB 256
#define HH 512
#define LLAYERS 3
#define TSTEPS 200
#define VV 100

typedef unsigned long long ull;

// ---------------- device scratch (no allocations allowed) ----------------
__device__ __align__(16) float g_wcomb[3u * 2048u * 1024u];   // 25.2 MB  [l][(j*4+gate)][k(x||h)]
__device__ __align__(16) float g_bcomb[3 * 2048];             // b_ih + b_hh, gate-interleaved
__device__ __align__(16) float g_h[2][3 * 256 * 512];         // double-buffered hidden states
__device__ __align__(16) float g_c[2][3 * 256 * 512];         // double-buffered cell states
__device__ __align__(16) float g_feat1[256 * 512];
__device__ __align__(16) float g_res[256u * 200u * 512u];     // [b][t][h]  105 MB
__device__ __align__(16) float g_hmid[51200u * 1024u];        // 210 MB

// ---------------- f32x2 packed helpers (Blackwell FFMA2 path) ----------------
__device__ __forceinline__ ull pk2(float a, float b) {
    ull r; asm("mov.b64 %0, {%1, %2};" : "=l"(r) : "f"(a), "f"(b)); return r;
}
__device__ __forceinline__ float2 upk2(ull v) {
    float2 r; asm("mov.b64 {%0, %1}, %2;" : "=f"(r.x), "=f"(r.y) : "l"(v)); return r;
}
__device__ __forceinline__ void fma2(ull& d, ull a, ull b) {
    asm("fma.rn.f32x2 %0, %1, %2, %0;" : "+l"(d) : "l"(a), "l"(b));
}

__device__ __forceinline__ float sigf(float x) { return 1.0f / (1.0f + expf(-x)); }
__device__ __forceinline__ float geluf(float x) { return 0.5f * x * (1.0f + erff(x * 0.70710678118654752f)); }

// ---------------- 64x64 tile accumulation core ----------------
// acc[p][c] packs rows (rbase + ty*8 + 2p, +1), col nbase + tx*4 + c.
// A: rows rbase..rbase+63, row stride lda (lda==0 => broadcast single row).
// B: output-col n reads B[n*ldb + k], k in [0,K). K must be a multiple of 32.
// smem: 2*32*64 floats (As k-major [32][64], Bs k-major [32][64]).
template<bool GUARDB>
__device__ __forceinline__ void gemm_acc(ull acc[4][4],
                                         const float* __restrict__ A, int lda,
                                         const float* __restrict__ B, int ldb,
                                         int K, int rbase, int nbase, int nlimit,
                                         float* smem)
{
    float* As = smem;
    float* Bs = smem + 32 * 64;
    const int tid = threadIdx.x;
    const int tx = tid & 15, ty = tid >> 4;
    const int nchunks = K >> 5;

    float4 pa[4], pb[4];
    // prefetch chunk 0
#pragma unroll
    for (int i = 0; i < 4; ++i) {
        int idx = i * 128 + tid;          // 0..511
        int row = idx >> 3, kg = idx & 7; // row in tile, float4 group in chunk
        pa[i] = *(const float4*)(A + (size_t)(rbase + row) * lda + kg * 4);
        int n = nbase + row;
        if (GUARDB && n >= nlimit) pb[i] = make_float4(0.f, 0.f, 0.f, 0.f);
        else                       pb[i] = *(const float4*)(B + (size_t)n * ldb + kg * 4);
    }

    for (int kc = 0; kc < nchunks; ++kc) {
        __syncthreads();   // previous chunk's consumers done
#pragma unroll
        for (int i = 0; i < 4; ++i) {
            int idx = i * 128 + tid;
            int row = idx >> 3, kg = idx & 7;
            As[(kg * 4 + 0) * 64 + row] = pa[i].x;
            As[(kg * 4 + 1) * 64 + row] = pa[i].y;
            As[(kg * 4 + 2) * 64 + row] = pa[i].z;
            As[(kg * 4 + 3) * 64 + row] = pa[i].w;
            Bs[(kg * 4 + 0) * 64 + row] = pb[i].x;
            Bs[(kg * 4 + 1) * 64 + row] = pb[i].y;
            Bs[(kg * 4 + 2) * 64 + row] = pb[i].z;
            Bs[(kg * 4 + 3) * 64 + row] = pb[i].w;
        }
        __syncthreads();

        if (kc + 1 < nchunks) {           // prefetch next chunk (overlaps compute)
            int k0 = (kc + 1) * 32;
#pragma unroll
            for (int i = 0; i < 4; ++i) {
                int idx = i * 128 + tid;
                int row = idx >> 3, kg = idx & 7;
                pa[i] = *(const float4*)(A + (size_t)(rbase + row) * lda + k0 + kg * 4);
                int n = nbase + row;
                if (GUARDB && n >= nlimit) pb[i] = make_float4(0.f, 0.f, 0.f, 0.f);
                else                       pb[i] = *(const float4*)(B + (size_t)n * ldb + k0 + kg * 4);
            }
        }

#pragma unroll
        for (int k = 0; k < 32; ++k) {
            ull a0 = *(const ull*)&As[k * 64 + ty * 8 + 0];
            ull a1 = *(const ull*)&As[k * 64 + ty * 8 + 2];
            ull a2 = *(const ull*)&As[k * 64 + ty * 8 + 4];
            ull a3 = *(const ull*)&As[k * 64 + ty * 8 + 6];
            float4 wv = *(const float4*)&Bs[k * 64 + tx * 4];
            ull w0 = pk2(wv.x, wv.x), w1 = pk2(wv.y, wv.y);
            ull w2 = pk2(wv.z, wv.z), w3 = pk2(wv.w, wv.w);
            fma2(acc[0][0], a0, w0); fma2(acc[0][1], a0, w1); fma2(acc[0][2], a0, w2); fma2(acc[0][3], a0, w3);
            fma2(acc[1][0], a1, w0); fma2(acc[1][1], a1, w1); fma2(acc[1][2], a1, w2); fma2(acc[1][3], a1, w3);
            fma2(acc[2][0], a2, w0); fma2(acc[2][1], a2, w1); fma2(acc[2][2], a2, w2); fma2(acc[2][3], a2, w3);
            fma2(acc[3][0], a3, w0); fma2(acc[3][1], a3, w1); fma2(acc[3][2], a3, w2); fma2(acc[3][3], a3, w3);
        }
    }
    __syncthreads();  // smem free for next use
}

// ---------------- generic 64x64-tiled GEMM: C = epi(A*B^T + bias) ----------------
// EPI: 0 = none, 1 = exact gelu
template<int EPI>
__global__ __launch_bounds__(128) void k_gemm64(const float* __restrict__ A, int lda,
                                                const float* __restrict__ B, int ldb,
                                                const float* __restrict__ bias,
                                                float* __restrict__ C, int ldc, int K)
{
    __shared__ float smem[2 * 32 * 64];
    ull acc[4][4] = {};
    const int rbase = blockIdx.y * 64;
    const int nbase = blockIdx.x * 64;
    gemm_acc<false>(acc, A, lda, B, ldb, K, rbase, nbase, 1 << 30, smem);

    const int tx = threadIdx.x & 15, ty = threadIdx.x >> 4;
#pragma unroll
    for (int p = 0; p < 4; ++p) {
        int r = rbase + ty * 8 + 2 * p;
#pragma unroll
        for (int c = 0; c < 4; ++c) {
            int n = nbase + tx * 4 + c;
            float2 v = upk2(acc[p][c]);
            float bz = bias[n];
            float x0 = v.x + bz, x1 = v.y + bz;
            if (EPI == 1) { x0 = geluf(x0); x1 = geluf(x1); }
            C[(size_t)r * ldc + n]       = x0;
            C[(size_t)(r + 1) * ldc + n] = x1;
        }
    }
}

// ---------------- final projection with transposed store out[b][v][t] ----------------
__global__ __launch_bounds__(128) void k_proj2(const float* __restrict__ A,   // g_hmid [51200][1024]
                                               const float* __restrict__ W2,  // [100][1024]
                                               const float* __restrict__ b2,
                                               float* __restrict__ out)
{
    __shared__ float smem[2 * 32 * 64];
    ull acc[4][4] = {};
    const int rbase = blockIdx.y * 64;
    const int nbase = blockIdx.x * 64;
    gemm_acc<true>(acc, A, 1024, W2, 1024, 1024, rbase, nbase, VV, smem);

    const int tx = threadIdx.x & 15, ty = threadIdx.x >> 4;
#pragma unroll
    for (int p = 0; p < 4; ++p) {
        int r0 = rbase + ty * 8 + 2 * p;
#pragma unroll
        for (int c = 0; c < 4; ++c) {
            int v = nbase + tx * 4 + c;
            if (v >= VV) continue;
            float2 val = upk2(acc[p][c]);
            float bz = b2[v];
#pragma unroll
            for (int q = 0; q < 2; ++q) {
                int r = r0 + q;
                int b = r / TSTEPS, t = r - b * TSTEPS;
                out[((size_t)b * VV + v) * TSTEPS + t] = (q ? val.y : val.x) + bz;
            }
        }
    }
}

// ---------------- weight reorder + c-state zero ----------------
// g_wcomb[l][j*4+gate][k] = k<512 ? w_ih[l][gate*512+j][k] : w_hh[l][gate*512+j][k-512]
__global__ void k_prep(const float* __restrict__ w_ih, const float* __restrict__ w_hh,
                       const float* __restrict__ b_ih, const float* __restrict__ b_hh)
{
    const size_t stride = (size_t)gridDim.x * blockDim.x;
    const size_t tid = (size_t)blockIdx.x * blockDim.x + threadIdx.x;
    const size_t nf4 = (size_t)3 * 2048 * 1024 / 4;
    for (size_t i = tid; i < nf4; i += stride) {
        size_t f = i * 4;
        int k  = (int)(f & 1023);
        size_t np = f >> 10;               // l*2048 + n'
        int l  = (int)(np >> 11);
        int n2 = (int)(np & 2047);
        int jj = n2 >> 2, g = n2 & 3;
        int n  = g * 512 + jj;
        const float* src = (k < 512) ? (w_ih + ((size_t)l * 2048 + n) * 512 + k)
                                     : (w_hh + ((size_t)l * 2048 + n) * 512 + (k - 512));
        *(float4*)&g_wcomb[f] = *(const float4*)src;
    }
    for (size_t i = tid; i < 3 * 2048; i += stride) {
        int l = (int)(i >> 11), n2 = (int)(i & 2047);
        int jj = n2 >> 2, g = n2 & 3;
        int n = g * 512 + jj;
        g_bcomb[i] = b_ih[(size_t)l * 2048 + n] + b_hh[(size_t)l * 2048 + n];
    }
    for (size_t i = tid; i < (size_t)3 * 256 * 512; i += stride) g_c[1][i] = 0.f;
}

// replicate h0 (written into g_h[1] layer 0) to layers 1 and 2
__global__ void k_repl()
{
    const int stride = gridDim.x * blockDim.x;
    for (int i = blockIdx.x * blockDim.x + threadIdx.x; i < 256 * 512; i += stride) {
        float v = g_h[1][i];
        g_h[1][256 * 512 + i]     = v;
        g_h[1][2 * 256 * 512 + i] = v;
    }
}

// ---------------- one recurrent (t, l) iteration: fused GEMM + LSTM cell ----------------
// Launched 600 times as separate graph nodes; stream order provides all
// inter-iteration synchronization (no grid barrier, no persistence).
__global__ __launch_bounds__(128) void k_step(const float* __restrict__ embed,
                                              const int* __restrict__ sidx,
                                              int t, int l)
{
    __shared__ float smem[2 * 32 * 64];
    const int mt = blockIdx.x >> 5;          // 0..3  (M tile: 64 batch rows)
    const int jt = blockIdx.x & 31;          // 0..31 (16 hidden units x 4 gates)
    const int rbase = mt * 64;
    const int nbase = jt * 64;
    const int tx = threadIdx.x & 15, ty = threadIdx.x >> 4;

    const int wpar = t & 1, rpar = wpar ^ 1;
    const float* W = g_wcomb + (size_t)l * 2048 * 1024;

    const float* xsrc; int xlda;
    if (l == 0) {
        if (t == 0) { xsrc = embed + (size_t)(*sidx) * 512; xlda = 0; }  // broadcast <sos>
        else        { xsrc = g_h[rpar] + 2 * 256 * 512; xlda = 512; }
    } else {
        xsrc = g_h[wpar] + (size_t)(l - 1) * 256 * 512; xlda = 512;
    }
    const float* hsrc = g_h[rpar] + (size_t)l * 256 * 512;

    ull acc[4][4] = {};
    gemm_acc<false>(acc, xsrc, xlda, W,       1024, 512, rbase, nbase, 1 << 30, smem);
    gemm_acc<false>(acc, hsrc, 512,  W + 512, 1024, 512, rbase, nbase, 1 << 30, smem);

    // fused LSTM cell epilogue: this thread owns hidden unit j for 8 batch rows
    const int j = jt * 16 + tx;
    const float bi = g_bcomb[l * 2048 + j * 4 + 0];
    const float bf = g_bcomb[l * 2048 + j * 4 + 1];
    const float bg = g_bcomb[l * 2048 + j * 4 + 2];
    const float bo = g_bcomb[l * 2048 + j * 4 + 3];
    const float* cprev = g_c[rpar] + (size_t)l * 256 * 512;
    float* cnew = g_c[wpar] + (size_t)l * 256 * 512;
    float* hnew = g_h[wpar] + (size_t)l * 256 * 512;

#pragma unroll
    for (int p = 0; p < 4; ++p) {
        float2 gi = upk2(acc[p][0]);
        float2 gf = upk2(acc[p][1]);
        float2 gg = upk2(acc[p][2]);
        float2 go = upk2(acc[p][3]);
        int r0 = rbase + ty * 8 + 2 * p;
#pragma unroll
        for (int q = 0; q < 2; ++q) {
            int r = r0 + q;
            float I = sigf((q ? gi.y : gi.x) + bi);
            float F = sigf((q ? gf.y : gf.x) + bf);
            float G = tanhf((q ? gg.y : gg.x) + bg);
            float O = sigf((q ? go.y : go.x) + bo);
            float cp = cprev[(size_t)r * 512 + j];
            float cn = F * cp + I * G;
            float hn = O * tanhf(cn);
            cnew[(size_t)r * 512 + j] = cn;
            hnew[(size_t)r * 512 + j] = hn;
            if (l == 2) g_res[((size_t)r * TSTEPS + t) * 512 + j] = hn;
        }
    }
}

// ---------------- host launcher ----------------
extern "C" void kernel_launch(void* const* d_in, const int* in_sizes, int n_in,
                              void* d_out, int out_size)
{
    (void)in_sizes; (void)n_in; (void)out_size;
    const float* feat  = (const float*)d_in[0];
    const float* vw    = (const float*)d_in[1];
    const float* vb    = (const float*)d_in[2];
    const float* embed = (const float*)d_in[3];
    const float* w_ih  = (const float*)d_in[4];
    const float* w_hh  = (const float*)d_in[5];
    const float* b_ih  = (const float*)d_in[6];
    const float* b_hh  = (const float*)d_in[7];
    const float* pw1   = (const float*)d_in[8];
    const float* pb1   = (const float*)d_in[9];
    const float* pw2   = (const float*)d_in[10];
    const float* pb2   = (const float*)d_in[11];
    const int*   sidx  = (const int*)d_in[12];
    float* out = (float*)d_out;

    float *s_feat1, *s_h, *s_res, *s_hmid;
    cudaGetSymbolAddress((void**)&s_feat1, g_feat1);
    cudaGetSymbolAddress((void**)&s_h, g_h);
    cudaGetSymbolAddress((void**)&s_res, g_res);
    cudaGetSymbolAddress((void**)&s_hmid, g_hmid);
    float* s_h1 = s_h + (size_t)3 * 256 * 512;   // g_h[1]

    // 1) reorder weights, combine biases, zero initial cell state
    k_prep<<<512, 256>>>(w_ih, w_hh, b_ih, b_hh);
    // 2) feat1 = feat @ Vw^T + vb
    k_gemm64<0><<<dim3(8, 4), 128>>>(feat, 512, vw, 512, vb, s_feat1, 512, 512);
    // 3) h0 = feat1 @ Vw^T + vb  -> g_h[1] layer 0
    k_gemm64<0><<<dim3(8, 4), 128>>>(s_feat1, 512, vw, 512, vb, s_h1, 512, 512);
    // 4) replicate h0 to layers 1, 2
    k_repl<<<256, 256>>>();
    // 5) 600 recurrent iterations, one launch each (stream order = sync)
    for (int t = 0; t < TSTEPS; ++t)
        for (int l = 0; l < LLAYERS; ++l)
            k_step<<<128, 128>>>(embed, sidx, t, l);
    // 6) hmid = gelu(res @ W1^T + b1)
    k_gemm64<1><<<dim3(16, 800), 128>>>(s_res, 512, pw1, 512, pb1, s_hmid, 1024, 512);
    // 7) logits -> out[b][v][t]
    k_proj2<<<dim3(2, 800), 128>>>(s_hmid, pw2, pb2, out);
}